// round 8
// baseline (speedup 1.0000x reference)
#include <cuda_runtime.h>
#include <math.h>
#include <stdint.h>

// Problem dims
#define N_TOK 2048
#define CDIM  1024
#define RH    256
#define NE    8
#define IDIM  4096
#define SEG   2048
#define R_EXP (NE*SEG)          // 16384
#define R_TOT (R_EXP + N_TOK)   // 18432
#define MT_TOT (R_TOT/128)      // 144 row tiles
#define KC 32
#define KSP 2                   // gemm2 K-split
#define NSTAGE 3

// SMEM layout: per stage [A_hi | A_lo | B_hi | B_lo]
#define OFF_TOK 64
#define OFF_BUF 1024
#define A_ROWB  80                     // 128 rows x (64B data + pad)
#define A_ARR   (128*A_ROWB)           // 10240
#define B_ROWB  528                    // 32 rows x (512B data + pad)
#define B_ARR   (32*B_ROWB)            // 16896
#define SBUF    (2*A_ARR + 2*B_ARR)    // 54272
#define SMEM_TOTAL (OFF_BUF + NSTAGE*SBUF)  // 163840

#define WPAIRS ((size_t)CDIM*IDIM/2)   // 2^21 float2-pairs per expert matrix

// Scratch (hi/lo packed as bf16x2 words, 2 elements per uint32)
__device__ uint32_t g_x_hi[N_TOK*CDIM/2],        g_x_lo[N_TOK*CDIM/2];
__device__ uint32_t g_w1_hi[9*WPAIRS],           g_w1_lo[9*WPAIRS];
__device__ uint32_t g_w2_hi[9*WPAIRS],           g_w2_lo[9*WPAIRS];
__device__ uint32_t g_h_hi[(size_t)R_TOT*IDIM/2], g_h_lo[(size_t)R_TOT*IDIM/2];
__device__ float    g_eo[(size_t)KSP*R_TOT*CDIM];
__device__ float    g_y1p[(size_t)8*N_TOK*RH];   // router split-K partials
__device__ int      g_cnt[NE];
__device__ int      g_ptok[R_EXP];
__device__ int      g_tpos[N_TOK*2];
__device__ float    g_tw[N_TOK*2];

// ---------------------------------------------------------------------------
// helpers (base sm_103-legal)
// ---------------------------------------------------------------------------
__device__ __forceinline__ void mma_bf16(float* d, const uint32_t* a, const uint32_t* b) {
    asm volatile(
        "mma.sync.aligned.m16n8k16.row.col.f32.bf16.bf16.f32 "
        "{%0,%1,%2,%3},{%4,%5,%6,%7},{%8,%9},{%0,%1,%2,%3};\n"
        : "+f"(d[0]), "+f"(d[1]), "+f"(d[2]), "+f"(d[3])
        : "r"(a[0]), "r"(a[1]), "r"(a[2]), "r"(a[3]), "r"(b[0]), "r"(b[1]));
}
#define LDMX4(r0,r1,r2,r3,addr) \
    asm volatile("ldmatrix.sync.aligned.m8n8.x4.shared.b16 {%0,%1,%2,%3}, [%4];" \
        : "=r"(r0),"=r"(r1),"=r"(r2),"=r"(r3) : "r"(addr))
#define LDMX4T(r0,r1,r2,r3,addr) \
    asm volatile("ldmatrix.sync.aligned.m8n8.x4.trans.shared.b16 {%0,%1,%2,%3}, [%4];" \
        : "=r"(r0),"=r"(r1),"=r"(r2),"=r"(r3) : "r"(addr))

// fp32 pair -> bf16x2 hi word + bf16x2 residual word (v0 in low half)
#define SPLIT2(hw, lw, v0, v1) do { \
    asm("cvt.rn.bf16x2.f32 %0, %1, %2;" : "=r"(hw) : "f"(v1), "f"(v0)); \
    float _h0 = __uint_as_float((hw) << 16); \
    float _h1 = __uint_as_float((hw) & 0xffff0000u); \
    float _r0 = (v0) - _h0, _r1 = (v1) - _h1; \
    asm("cvt.rn.bf16x2.f32 %0, %1, %2;" : "=r"(lw) : "f"(_r1), "f"(_r0)); \
} while (0)

__device__ __forceinline__ uint32_t smem_u32(const void* p) {
    uint32_t a;
    asm("{ .reg .u64 t; cvta.to.shared.u64 t, %1; cvt.u32.u64 %0, t; }"
        : "=r"(a) : "l"(p));
    return a;
}
#define CP16(dst, src) asm volatile("cp.async.ca.shared.global [%0], [%1], 16;"::"r"(dst),"l"(src))
#define CP_COMMIT()    asm volatile("cp.async.commit_group;")
#define CP_WAIT1()     asm volatile("cp.async.wait_group 1;")

// ---------------------------------------------------------------------------
// GEMM core: CTA tile 128m x 256n, 8 warps (2m x 4n), warp tile 64x64,
// 3-term bf16, 3-stage cp.async pipeline, term-reordered MMAs.
// ---------------------------------------------------------------------------
#define FILLC(cc) do {                                                         \
    uint32_t _bo = (uint32_t)((cc) % NSTAGE) * SBUF;                           \
    const char* _s = a_hi + (size_t)(cc) * 64;                                 \
    CP16(a_dst + _bo,           _s);      CP16(a_dst + _bo + 16,        _s + 16); \
    _s = a_lo + (size_t)(cc) * 64;                                             \
    CP16(a_dst + _bo + A_ARR,   _s);      CP16(a_dst + _bo + A_ARR + 16, _s + 16); \
    _s = b_hi + (size_t)(cc) * bstep;                                          \
    CP16(b_dst + _bo,      _s);      CP16(b_dst + _bo + 16, _s + 16);          \
    CP16(b_dst + _bo + 32, _s + 32); CP16(b_dst + _bo + 48, _s + 48);          \
    _s = b_lo + (size_t)(cc) * bstep;                                          \
    CP16(b_dst + _bo + B_ARR,      _s);      CP16(b_dst + _bo + B_ARR + 16, _s + 16); \
    CP16(b_dst + _bo + B_ARR + 32, _s + 32); CP16(b_dst + _bo + B_ARR + 48, _s + 48); \
    CP_COMMIT();                                                               \
} while (0)

#define GEMM_CORE(NCH, BSTEP)                                                  \
    const int wid = tid >> 5, lane = tid & 31;                                 \
    const int wm = wid & 1, wn = wid >> 1;                                     \
    const size_t bstep = (BSTEP);                                              \
    const uint32_t a_dst = smem_base + OFF_BUF                                 \
        + (uint32_t)((tid >> 1) * A_ROWB + (tid & 1) * 32);                    \
    const uint32_t b_dst = smem_base + OFF_BUF + 2*A_ARR                       \
        + (uint32_t)((tid >> 3) * B_ROWB + (tid & 7) * 64);                    \
    const uint32_t a_lm = smem_base + OFF_BUF                                  \
        + (uint32_t)((wm * 64 + (lane & 15)) * A_ROWB + (lane >> 4) * 16);     \
    const uint32_t b_lm = smem_base + OFF_BUF + 2*A_ARR                        \
        + (uint32_t)(((lane & 7) + ((lane >> 3) & 1) * 8) * B_ROWB             \
                     + (lane >> 4) * B_ARR + wn * 128);                        \
    float acc[4][8][4];                                                        \
    _Pragma("unroll")                                                          \
    for (int i = 0; i < 4; i++)                                                \
        _Pragma("unroll")                                                      \
        for (int j = 0; j < 8; j++)                                            \
            _Pragma("unroll")                                                  \
            for (int q = 0; q < 4; q++) acc[i][j][q] = 0.0f;                   \
    FILLC(0);                                                                  \
    FILLC(1);                                                                  \
    for (int c = 0; c < (NCH); c++) {                                          \
        const uint32_t bo = (uint32_t)(c % NSTAGE) * SBUF;                     \
        CP_WAIT1();                                                            \
        __syncthreads();                                                       \
        if (c + 2 < (NCH)) { FILLC(c + 2); } else { CP_COMMIT(); }             \
        _Pragma("unroll")                                                      \
        for (int slab = 0; slab < 2; slab++) {                                 \
            uint32_t ah[4][4], al[4][4];                                       \
            _Pragma("unroll")                                                  \
            for (int i = 0; i < 4; i++) {                                      \
                uint32_t aa = a_lm + bo + (uint32_t)(i * (16 * A_ROWB) + slab * 32); \
                LDMX4(ah[i][0], ah[i][1], ah[i][2], ah[i][3], aa);             \
                LDMX4(al[i][0], al[i][1], al[i][2], al[i][3], aa + A_ARR);     \
            }                                                                  \
            _Pragma("unroll")                                                  \
            for (int jp = 0; jp < 4; jp++) {                                   \
                uint32_t bb0[4], bb1[4];                                       \
                uint32_t ba = b_lm + bo + (uint32_t)(slab * (16 * B_ROWB) + jp * 32); \
                LDMX4T(bb0[0], bb0[1], bb0[2], bb0[3], ba);                    \
                LDMX4T(bb1[0], bb1[1], bb1[2], bb1[3], ba + 16);               \
                _Pragma("unroll")                                              \
                for (int i = 0; i < 4; i++) {                                  \
                    mma_bf16(acc[i][2*jp],   ah[i], bb0);                      \
                    mma_bf16(acc[i][2*jp+1], ah[i], bb1);                      \
                }                                                              \
                _Pragma("unroll")                                              \
                for (int i = 0; i < 4; i++) {                                  \
                    mma_bf16(acc[i][2*jp],   al[i], bb0);                      \
                    mma_bf16(acc[i][2*jp+1], al[i], bb1);                      \
                }                                                              \
                _Pragma("unroll")                                              \
                for (int i = 0; i < 4; i++) {                                  \
                    mma_bf16(acc[i][2*jp],   ah[i], bb0 + 2);                  \
                    mma_bf16(acc[i][2*jp+1], ah[i], bb1 + 2);                  \
                }                                                              \
            }                                                                  \
        }                                                                      \
    }

// ---------------------------------------------------------------------------
// 0) init counters
// ---------------------------------------------------------------------------
__global__ void init_kernel() {
    if (threadIdx.x < NE) g_cnt[threadIdx.x] = 0;
}

// ---------------------------------------------------------------------------
// 0b) split kernels: fp32 -> bf16 hi/lo packed words
// ---------------------------------------------------------------------------
__global__ void split_x_k(const float* __restrict__ x) {
    size_t p = ((size_t)blockIdx.x * 256 + threadIdx.x) * 2;   // pair index
    float4 v = *(const float4*)((const float2*)x + p);
    uint32_t h0, l0, h1, l1;
    SPLIT2(h0, l0, v.x, v.y);
    SPLIT2(h1, l1, v.z, v.w);
    *(uint2*)(g_x_hi + p) = make_uint2(h0, h1);
    *(uint2*)(g_x_lo + p) = make_uint2(l0, l1);
}

__global__ void split_w_k(const float* __restrict__ ew,
                          const float* __restrict__ sw, int which) {
    size_t p = ((size_t)blockIdx.x * 256 + threadIdx.x) * 2;   // pair index
    size_t e = p >> 21, off = p & (WPAIRS - 1);
    float4 v = (e < 8) ? *(const float4*)((const float2*)ew + e * WPAIRS + off)
                       : *(const float4*)((const float2*)sw + off);
    uint32_t h0, l0, h1, l1;
    SPLIT2(h0, l0, v.x, v.y);
    SPLIT2(h1, l1, v.z, v.w);
    uint32_t* hi = which ? g_w2_hi : g_w1_hi;
    uint32_t* lo = which ? g_w2_lo : g_w1_lo;
    *(uint2*)(hi + p) = make_uint2(h0, h1);
    *(uint2*)(lo + p) = make_uint2(l0, l1);
}

// ---------------------------------------------------------------------------
// 1) router GEMM split-K=8 (deterministic partials)
// ---------------------------------------------------------------------------
__global__ void __launch_bounds__(256, 2)
router_gemm(const float* __restrict__ x, const float* __restrict__ rw1) {
    __shared__ float As[8][128];
    __shared__ float Bs[8][128];
    const int tid = threadIdx.x;
    const int m0 = blockIdx.y * 128;
    const int n0 = blockIdx.x * 128;
    const int ks = blockIdx.z * 128;

    const int ar = tid >> 1, kh = (tid & 1) * 4;
    const int kb = tid >> 5, bn = (tid & 31) * 4;
    const float* arow = x + (size_t)(m0 + ar) * CDIM + ks;
    const float* bptr = rw1 + (size_t)(ks + kb) * RH + n0 + bn;
    const int tm = (tid >> 4) * 8, tn = (tid & 15) * 8;

    float acc[8][8];
#pragma unroll
    for (int i = 0; i < 8; i++)
#pragma unroll
        for (int j = 0; j < 8; j++) acc[i][j] = 0.0f;

    for (int k0 = 0; k0 < 128; k0 += 8) {
        float4 av = *(const float4*)(arow + k0 + kh);
        As[kh + 0][ar] = av.x; As[kh + 1][ar] = av.y;
        As[kh + 2][ar] = av.z; As[kh + 3][ar] = av.w;
        *(float4*)&Bs[kb][bn] = *(const float4*)(bptr + (size_t)k0 * RH);
        __syncthreads();
#pragma unroll
        for (int kk = 0; kk < 8; kk++) {
            float a[8], b[8];
#pragma unroll
            for (int i = 0; i < 8; i++) a[i] = As[kk][tm + i];
#pragma unroll
            for (int j = 0; j < 8; j++) b[j] = Bs[kk][tn + j];
#pragma unroll
            for (int i = 0; i < 8; i++)
#pragma unroll
                for (int j = 0; j < 8; j++) acc[i][j] += a[i] * b[j];
        }
        __syncthreads();
    }
#pragma unroll
    for (int i = 0; i < 8; i++) {
        float* dst = g_y1p + ((size_t)blockIdx.z * N_TOK + m0 + tm + i) * RH + n0 + tn;
#pragma unroll
        for (int j = 0; j < 8; j++) dst[j] = acc[i][j];
    }
}

// ---------------------------------------------------------------------------
// 2) routing: sum partials, +rb1, relu, @rw2+rb2, softmax, top2, scatter
// ---------------------------------------------------------------------------
__global__ void route_kernel(const float* __restrict__ rw2,
                             const float* __restrict__ rb2,
                             const float* __restrict__ rb1) {
    __shared__ float s_w[RH * NE];
    __shared__ float s_b[NE];
    __shared__ float s_b1[RH];
    const int tid = threadIdx.x;
    for (int i = tid; i < RH * NE; i += 256) s_w[i] = rw2[i];
    if (tid < NE) s_b[tid] = rb2[tid];
    if (tid < RH) s_b1[tid] = rb1[tid];
    __syncthreads();

    const int n = blockIdx.x * 256 + tid;

    float acc[NE];
#pragma unroll
    for (int e = 0; e < NE; e++) acc[e] = s_b[e];
    for (int c = 0; c < RH; c++) {
        float vv = 0.0f;
#pragma unroll
        for (int s = 0; s < 8; s++)
            vv += g_y1p[((size_t)s * N_TOK + n) * RH + c];
        float v = fmaxf(vv + s_b1[c], 0.0f);
#pragma unroll
        for (int e = 0; e < NE; e++) acc[e] += v * s_w[c * NE + e];
    }

    float m = acc[0];
#pragma unroll
    for (int e = 1; e < NE; e++) m = fmaxf(m, acc[e]);
    float s = 0.0f, g[NE];
#pragma unroll
    for (int e = 0; e < NE; e++) { g[e] = expf(acc[e] - m); s += g[e]; }
    float inv = 1.0f / s;
#pragma unroll
    for (int e = 0; e < NE; e++) g[e] *= inv;

    int i1 = 0; float g1 = g[0];
#pragma unroll
    for (int e = 1; e < NE; e++) if (g[e] > g1) { g1 = g[e]; i1 = e; }
    int i2 = -1; float g2 = -1.0f;
#pragma unroll
    for (int e = 0; e < NE; e++)
        if (e != i1 && g[e] > g2) { g2 = g[e]; i2 = e; }

    float t  = expf((g2 - g1) * 0.5f);
    float d  = 1.0f / (1.0f + t);
    float w1 = d, w2 = t * d;

    int p1 = atomicAdd(&g_cnt[i1], 1);
    g_ptok[i1 * SEG + p1] = n;
    g_tpos[n * 2] = i1 * SEG + p1; g_tw[n * 2] = w1;
    int p2 = atomicAdd(&g_cnt[i2], 1);
    g_ptok[i2 * SEG + p2] = n;
    g_tpos[n * 2 + 1] = i2 * SEG + p2; g_tw[n * 2 + 1] = w2;
}

// ---------------------------------------------------------------------------
// 3) grouped GEMM1: h = silu(gather(x) @ W1 + b1), split stored.
//    grid (IDIM/256=16, 144), 256 threads.
// ---------------------------------------------------------------------------
__global__ void __launch_bounds__(256)
gemm1_k(const float* __restrict__ eb1, const float* __restrict__ sb1) {
    extern __shared__ char smem[];
    const int t = blockIdx.y, n0 = blockIdx.x * 256, tid = threadIdx.x;
    int* s_tok = (int*)(smem + OFF_TOK);

    int e;
    if (t < 128) {
        e = t >> 4;
        int cnt = g_cnt[e];
        int lr0 = (t & 15) * 128;
        if (lr0 >= cnt) return;
        if (tid < 128) {
            int lr = lr0 + tid;
            s_tok[tid] = (lr < cnt) ? g_ptok[e * SEG + lr] : 0;
        }
    } else {
        e = 8;
        if (tid < 128) s_tok[tid] = (t - 128) * 128 + tid;
    }
    __syncthreads();

    const uint32_t smem_base = smem_u32(smem);
    const int tok = s_tok[tid >> 1];
    const char* a_hi = (const char*)g_x_hi + (size_t)tok * CDIM * 2 + (tid & 1) * 32;
    const char* a_lo = (const char*)g_x_lo + (size_t)tok * CDIM * 2 + (tid & 1) * 32;
    const size_t bofs = (((size_t)e * CDIM + (tid >> 3)) * IDIM + n0) * 2 + (tid & 7) * 64;
    const char* b_hi = (const char*)g_w1_hi + bofs;
    const char* b_lo = (const char*)g_w1_lo + bofs;

    GEMM_CORE(CDIM / KC, (size_t)KC * IDIM * 2)

    const float* bias = (e < 8) ? eb1 + (size_t)e * IDIM : sb1;
#pragma unroll
    for (int i = 0; i < 4; i++)
#pragma unroll
        for (int j = 0; j < 8; j++) {
            const int row0 = t * 128 + wm * 64 + i * 16 + (lane >> 2);
            const int col  = n0 + wn * 64 + j * 8 + (lane & 3) * 2;
            float b0 = bias[col], b1 = bias[col + 1];
            float v0 = acc[i][j][0] + b0, v1 = acc[i][j][1] + b1;
            float v2 = acc[i][j][2] + b0, v3 = acc[i][j][3] + b1;
            v0 = v0 / (1.0f + __expf(-v0));
            v1 = v1 / (1.0f + __expf(-v1));
            v2 = v2 / (1.0f + __expf(-v2));
            v3 = v3 / (1.0f + __expf(-v3));
            uint32_t hw, lw;
            size_t idx = ((size_t)row0 * IDIM + col) >> 1;
            SPLIT2(hw, lw, v0, v1);
            g_h_hi[idx] = hw; g_h_lo[idx] = lw;
            size_t idx2 = idx + (size_t)4 * IDIM;   // +8 rows
            SPLIT2(hw, lw, v2, v3);
            g_h_hi[idx2] = hw; g_h_lo[idx2] = lw;
        }
}

// ---------------------------------------------------------------------------
// 4) grouped GEMM2 (K-split 2): eo[part] = h[:,kpart] @ W2[kpart,:] (+b2 on part0)
//    grid (CDIM/256=4, 144, 2), 256 threads.
// ---------------------------------------------------------------------------
__global__ void __launch_bounds__(256)
gemm2_k(const float* __restrict__ eb2, const float* __restrict__ sb2) {
    extern __shared__ char smem[];
    const int t = blockIdx.y, n0 = blockIdx.x * 256, part = blockIdx.z;
    const int tid = threadIdx.x;

    int e;
    if (t < 128) {
        e = t >> 4;
        if ((t & 15) * 128 >= g_cnt[e]) return;
    } else {
        e = 8;
    }

    const uint32_t smem_base = smem_u32(smem);
    const int kpart = part * (IDIM / KSP);
    const int r = t * 128 + (tid >> 1);
    const char* a_hi = (const char*)g_h_hi + ((size_t)r * IDIM + kpart) * 2 + (tid & 1) * 32;
    const char* a_lo = (const char*)g_h_lo + ((size_t)r * IDIM + kpart) * 2 + (tid & 1) * 32;
    const size_t bofs = (((size_t)e * IDIM + kpart + (tid >> 3)) * CDIM + n0) * 2 + (tid & 7) * 64;
    const char* b_hi = (const char*)g_w2_hi + bofs;
    const char* b_lo = (const char*)g_w2_lo + bofs;

    GEMM_CORE(IDIM / KSP / KC, (size_t)KC * CDIM * 2)

    float* eo = g_eo + (size_t)part * R_TOT * CDIM;
    const float* bias = (part == 0) ? ((e < 8) ? eb2 + (size_t)e * CDIM : sb2) : (const float*)0;
#pragma unroll
    for (int i = 0; i < 4; i++)
#pragma unroll
        for (int j = 0; j < 8; j++) {
            const int row0 = t * 128 + wm * 64 + i * 16 + (lane >> 2);
            const int col  = n0 + wn * 64 + j * 8 + (lane & 3) * 2;
            float b0 = bias ? bias[col] : 0.0f;
            float b1 = bias ? bias[col + 1] : 0.0f;
            float2 lo, hi;
            lo.x = acc[i][j][0] + b0; lo.y = acc[i][j][1] + b1;
            hi.x = acc[i][j][2] + b0; hi.y = acc[i][j][3] + b1;
            *(float2*)(eo + (size_t)row0 * CDIM + col) = lo;
            *(float2*)(eo + (size_t)(row0 + 8) * CDIM + col) = hi;
        }
}

// ---------------------------------------------------------------------------
// 5) combine: out[n] = Σp eo[p][shared] + w0 Σp eo[p][pos0] + w1 Σp eo[p][pos1]
// ---------------------------------------------------------------------------
__global__ void combine_kernel(float* __restrict__ out) {
    int gid = blockIdx.x * 256 + threadIdx.x;
    int n = gid >> 8, c4 = gid & 255;
    const float4* e0 = (const float4*)g_eo;
    const float4* e1 = e0 + (size_t)R_TOT * (CDIM / 4);
    size_t sh = (size_t)(R_EXP + n) * (CDIM / 4) + c4;
    float4 o0 = e0[sh], o1 = e1[sh];
    int   p0 = g_tpos[n * 2],     p1 = g_tpos[n * 2 + 1];
    float w0 = g_tw[n * 2],       w1 = g_tw[n * 2 + 1];
    size_t i0 = (size_t)p0 * (CDIM / 4) + c4;
    size_t i1 = (size_t)p1 * (CDIM / 4) + c4;
    float4 a0 = e0[i0], a1 = e1[i0];
    float4 b0 = e0[i1], b1 = e1[i1];
    float4 o;
    o.x = o0.x + o1.x + w0 * (a0.x + a1.x) + w1 * (b0.x + b1.x);
    o.y = o0.y + o1.y + w0 * (a0.y + a1.y) + w1 * (b0.y + b1.y);
    o.z = o0.z + o1.z + w0 * (a0.z + a1.z) + w1 * (b0.z + b1.z);
    o.w = o0.w + o1.w + w0 * (a0.w + a1.w) + w1 * (b0.w + b1.w);
    ((float4*)out)[gid] = o;
}

// ---------------------------------------------------------------------------
extern "C" void kernel_launch(void* const* d_in, const int* in_sizes, int n_in,
                              void* d_out, int out_size) {
    const float* x   = (const float*)d_in[0];
    const float* rw1 = (const float*)d_in[1];
    const float* rb1 = (const float*)d_in[2];
    const float* rw2 = (const float*)d_in[3];
    const float* rb2 = (const float*)d_in[4];
    const float* ew1 = (const float*)d_in[5];
    const float* eb1 = (const float*)d_in[6];
    const float* ew2 = (const float*)d_in[7];
    const float* eb2 = (const float*)d_in[8];
    const float* sw1 = (const float*)d_in[9];
    const float* sb1 = (const float*)d_in[10];
    const float* sw2 = (const float*)d_in[11];
    const float* sb2 = (const float*)d_in[12];
    float* out = (float*)d_out;

    static bool attr_done = false;
    if (!attr_done) {
        cudaFuncSetAttribute(gemm1_k, cudaFuncAttributeMaxDynamicSharedMemorySize, SMEM_TOTAL);
        cudaFuncSetAttribute(gemm2_k, cudaFuncAttributeMaxDynamicSharedMemorySize, SMEM_TOTAL);
        attr_done = true;
    }

    init_kernel<<<1, 32>>>();
    split_x_k<<<N_TOK * CDIM / 4 / 256, 256>>>(x);
    split_w_k<<<(int)(9 * WPAIRS / 2 / 256), 256>>>(ew1, sw1, 0);
    split_w_k<<<(int)(9 * WPAIRS / 2 / 256), 256>>>(ew2, sw2, 1);
    router_gemm<<<dim3(2, 16, 8), 256>>>(x, rw1);
    route_kernel<<<8, 256>>>(rw2, rb2, rb1);
    gemm1_k<<<dim3(IDIM / 256, MT_TOT), 256, SMEM_TOTAL>>>(eb1, sb1);
    gemm2_k<<<dim3(CDIM / 256, MT_TOT, KSP), 256, SMEM_TOTAL>>>(eb2, sb2);
    combine_kernel<<<N_TOK * CDIM / 4 / 256, 256>>>(out);
}

// round 9
// speedup vs baseline: 1.0219x; 1.0219x over previous
#include <cuda_runtime.h>
#include <math.h>
#include <stdint.h>

// Problem dims
#define N_TOK 2048
#define CDIM  1024
#define RH    256
#define NE    8
#define IDIM  4096
#define SEG   2048
#define R_EXP (NE*SEG)          // 16384
#define R_TOT (R_EXP + N_TOK)   // 18432
#define MT_TOT (R_TOT/128)      // 144 row tiles
#define KC 32

// SMEM layout: per stage [A_hi | A_lo | B_hi | B_lo]
// A: 128 rows x 80B (64B data + pad); B: 32 k-rows x 272B (256B data + pad)
#define OFF_TOK 64
#define OFF_BUF 1024
#define A_ROWB  80
#define A_ARR   (128*A_ROWB)           // 10240
#define B_ROWB  272
#define B_ARR   (32*B_ROWB)            // 8704
#define SBUF    (2*A_ARR + 2*B_ARR)    // 37888
#define NSTAGE  2
#define SMEM_TOTAL (OFF_BUF + NSTAGE*SBUF)  // 76800  (x2 CTAs = 153600/SM)

#define WPAIRS ((size_t)CDIM*IDIM/2)   // 2^21 float2-pairs per expert matrix

// Scratch (hi/lo packed as bf16x2 words, 2 elements per uint32)
__device__ uint32_t g_x_hi[N_TOK*CDIM/2],        g_x_lo[N_TOK*CDIM/2];
__device__ uint32_t g_w1_hi[9*WPAIRS],           g_w1_lo[9*WPAIRS];
__device__ uint32_t g_w2_hi[9*WPAIRS],           g_w2_lo[9*WPAIRS];
__device__ uint32_t g_h_hi[(size_t)R_TOT*IDIM/2], g_h_lo[(size_t)R_TOT*IDIM/2];
__device__ float    g_eo[(size_t)R_TOT*CDIM];
__device__ float    g_y1p[(size_t)8*N_TOK*RH];   // router split-K partials
__device__ int      g_cnt[NE];
__device__ int      g_ptok[R_EXP];
__device__ int      g_tpos[N_TOK*2];
__device__ float    g_tw[N_TOK*2];

// ---------------------------------------------------------------------------
// helpers (base sm_103-legal)
// ---------------------------------------------------------------------------
__device__ __forceinline__ void mma_bf16(float* d, const uint32_t* a, const uint32_t* b) {
    asm volatile(
        "mma.sync.aligned.m16n8k16.row.col.f32.bf16.bf16.f32 "
        "{%0,%1,%2,%3},{%4,%5,%6,%7},{%8,%9},{%0,%1,%2,%3};\n"
        : "+f"(d[0]), "+f"(d[1]), "+f"(d[2]), "+f"(d[3])
        : "r"(a[0]), "r"(a[1]), "r"(a[2]), "r"(a[3]), "r"(b[0]), "r"(b[1]));
}
#define LDMX4(r0,r1,r2,r3,addr) \
    asm volatile("ldmatrix.sync.aligned.m8n8.x4.shared.b16 {%0,%1,%2,%3}, [%4];" \
        : "=r"(r0),"=r"(r1),"=r"(r2),"=r"(r3) : "r"(addr))
#define LDMX2T(r0,r1,addr) \
    asm volatile("ldmatrix.sync.aligned.m8n8.x2.trans.shared.b16 {%0,%1}, [%2];" \
        : "=r"(r0),"=r"(r1) : "r"(addr))

// fp32 pair -> bf16x2 hi word + bf16x2 residual word (v0 in low half)
#define SPLIT2(hw, lw, v0, v1) do { \
    asm("cvt.rn.bf16x2.f32 %0, %1, %2;" : "=r"(hw) : "f"(v1), "f"(v0)); \
    float _h0 = __uint_as_float((hw) << 16); \
    float _h1 = __uint_as_float((hw) & 0xffff0000u); \
    float _r0 = (v0) - _h0, _r1 = (v1) - _h1; \
    asm("cvt.rn.bf16x2.f32 %0, %1, %2;" : "=r"(lw) : "f"(_r1), "f"(_r0)); \
} while (0)

__device__ __forceinline__ uint32_t smem_u32(const void* p) {
    uint32_t a;
    asm("{ .reg .u64 t; cvta.to.shared.u64 t, %1; cvt.u32.u64 %0, t; }"
        : "=r"(a) : "l"(p));
    return a;
}
#define CP16(dst, src) asm volatile("cp.async.ca.shared.global [%0], [%1], 16;"::"r"(dst),"l"(src))
#define CP_COMMIT()    asm volatile("cp.async.commit_group;")
#define CP_WAIT0()     asm volatile("cp.async.wait_group 0;")

// ---------------------------------------------------------------------------
// GEMM core: CTA 128m x 128n, 8 warps (4m x 2n), warp tile 32x64,
// 3-term bf16, 2-stage cp.async, R6-validated fragment schedule.
// Needs in scope: tid, smem_base, a_hi/a_lo/b_hi/b_lo (per-thread chunk-0
// byte pointers). Declares wm, wn, lane, acc[2][8][4].
// ---------------------------------------------------------------------------
#define FILLC(cc) do {                                                         \
    uint32_t _bo = (uint32_t)((cc) & 1) * SBUF;                                \
    const char* _s = a_hi + (size_t)(cc) * 64;                                 \
    CP16(a_dst + _bo,          _s);      CP16(a_dst + _bo + 16,        _s + 16); \
    _s = a_lo + (size_t)(cc) * 64;                                             \
    CP16(a_dst + _bo + A_ARR,  _s);      CP16(a_dst + _bo + A_ARR + 16, _s + 16); \
    _s = b_hi + (size_t)(cc) * bstep;                                          \
    CP16(b_dst + _bo,          _s);      CP16(b_dst + _bo + 16,        _s + 16); \
    _s = b_lo + (size_t)(cc) * bstep;                                          \
    CP16(b_dst + _bo + B_ARR,  _s);      CP16(b_dst + _bo + B_ARR + 16, _s + 16); \
    CP_COMMIT();                                                               \
} while (0)

#define GEMM_CORE(NCH, BSTEP)                                                  \
    const int wid = tid >> 5, lane = tid & 31;                                 \
    const int wm = wid & 3, wn = wid >> 2;                                     \
    const size_t bstep = (BSTEP);                                              \
    const uint32_t a_dst = smem_base + OFF_BUF                                 \
        + (uint32_t)((tid >> 1) * A_ROWB + (tid & 1) * 32);                    \
    const uint32_t b_dst = smem_base + OFF_BUF + 2*A_ARR                       \
        + (uint32_t)((tid >> 3) * B_ROWB + (tid & 7) * 32);                    \
    const uint32_t a_lm = smem_base + OFF_BUF                                  \
        + (uint32_t)((wm * 32 + (lane & 15)) * A_ROWB + (lane >> 4) * 16);     \
    const uint32_t b_lm = smem_base + OFF_BUF + 2*A_ARR                        \
        + (uint32_t)((lane & 15) * B_ROWB + wn * 128);                         \
    float acc[2][8][4];                                                        \
    _Pragma("unroll")                                                          \
    for (int i = 0; i < 2; i++)                                                \
        _Pragma("unroll")                                                      \
        for (int j = 0; j < 8; j++)                                            \
            _Pragma("unroll")                                                  \
            for (int q = 0; q < 4; q++) acc[i][j][q] = 0.0f;                   \
    FILLC(0);                                                                  \
    for (int c = 0; c < (NCH); c++) {                                          \
        const uint32_t bo = (uint32_t)(c & 1) * SBUF;                          \
        CP_WAIT0();                                                            \
        __syncthreads();                                                       \
        if (c + 1 < (NCH)) { FILLC(c + 1); }                                   \
        _Pragma("unroll")                                                      \
        for (int slab = 0; slab < 2; slab++) {                                 \
            uint32_t ah[2][4], al[2][4];                                       \
            _Pragma("unroll")                                                  \
            for (int i = 0; i < 2; i++) {                                      \
                uint32_t aa = a_lm + bo + (uint32_t)(i * (16 * A_ROWB) + slab * 32); \
                LDMX4(ah[i][0], ah[i][1], ah[i][2], ah[i][3], aa);             \
                LDMX4(al[i][0], al[i][1], al[i][2], al[i][3], aa + A_ARR);     \
            }                                                                  \
            _Pragma("unroll")                                                  \
            for (int j = 0; j < 8; j++) {                                      \
                uint32_t bh[2], bl[2];                                         \
                uint32_t ba = b_lm + bo + (uint32_t)(slab * (16 * B_ROWB) + j * 16); \
                LDMX2T(bh[0], bh[1], ba);                                      \
                LDMX2T(bl[0], bl[1], ba + B_ARR);                              \
                _Pragma("unroll")                                              \
                for (int i = 0; i < 2; i++) {                                  \
                    mma_bf16(acc[i][j], ah[i], bh);                            \
                    mma_bf16(acc[i][j], al[i], bh);                            \
                    mma_bf16(acc[i][j], ah[i], bl);                            \
                }                                                              \
            }                                                                  \
        }                                                                      \
    }

// ---------------------------------------------------------------------------
// 0) init counters
// ---------------------------------------------------------------------------
__global__ void init_kernel() {
    if (threadIdx.x < NE) g_cnt[threadIdx.x] = 0;
}

// ---------------------------------------------------------------------------
// 0b) split kernels: fp32 -> bf16 hi/lo packed words (float4 loads)
// ---------------------------------------------------------------------------
__global__ void split_x_k(const float* __restrict__ x) {
    size_t p = ((size_t)blockIdx.x * 256 + threadIdx.x) * 2;
    float4 v = *(const float4*)((const float2*)x + p);
    uint32_t h0, l0, h1, l1;
    SPLIT2(h0, l0, v.x, v.y);
    SPLIT2(h1, l1, v.z, v.w);
    *(uint2*)(g_x_hi + p) = make_uint2(h0, h1);
    *(uint2*)(g_x_lo + p) = make_uint2(l0, l1);
}

__global__ void split_w_k(const float* __restrict__ ew,
                          const float* __restrict__ sw, int which) {
    size_t p = ((size_t)blockIdx.x * 256 + threadIdx.x) * 2;
    size_t e = p >> 21, off = p & (WPAIRS - 1);
    float4 v = (e < 8) ? *(const float4*)((const float2*)ew + e * WPAIRS + off)
                       : *(const float4*)((const float2*)sw + off);
    uint32_t h0, l0, h1, l1;
    SPLIT2(h0, l0, v.x, v.y);
    SPLIT2(h1, l1, v.z, v.w);
    uint32_t* hi = which ? g_w2_hi : g_w1_hi;
    uint32_t* lo = which ? g_w2_lo : g_w1_lo;
    *(uint2*)(hi + p) = make_uint2(h0, h1);
    *(uint2*)(lo + p) = make_uint2(l0, l1);
}

// ---------------------------------------------------------------------------
// 1) router GEMM split-K=8 (deterministic partials)
// ---------------------------------------------------------------------------
__global__ void __launch_bounds__(256, 2)
router_gemm(const float* __restrict__ x, const float* __restrict__ rw1) {
    __shared__ float As[8][128];
    __shared__ float Bs[8][128];
    const int tid = threadIdx.x;
    const int m0 = blockIdx.y * 128;
    const int n0 = blockIdx.x * 128;
    const int ks = blockIdx.z * 128;

    const int ar = tid >> 1, kh = (tid & 1) * 4;
    const int kb = tid >> 5, bn = (tid & 31) * 4;
    const float* arow = x + (size_t)(m0 + ar) * CDIM + ks;
    const float* bptr = rw1 + (size_t)(ks + kb) * RH + n0 + bn;
    const int tm = (tid >> 4) * 8, tn = (tid & 15) * 8;

    float acc[8][8];
#pragma unroll
    for (int i = 0; i < 8; i++)
#pragma unroll
        for (int j = 0; j < 8; j++) acc[i][j] = 0.0f;

    for (int k0 = 0; k0 < 128; k0 += 8) {
        float4 av = *(const float4*)(arow + k0 + kh);
        As[kh + 0][ar] = av.x; As[kh + 1][ar] = av.y;
        As[kh + 2][ar] = av.z; As[kh + 3][ar] = av.w;
        *(float4*)&Bs[kb][bn] = *(const float4*)(bptr + (size_t)k0 * RH);
        __syncthreads();
#pragma unroll
        for (int kk = 0; kk < 8; kk++) {
            float a[8], b[8];
#pragma unroll
            for (int i = 0; i < 8; i++) a[i] = As[kk][tm + i];
#pragma unroll
            for (int j = 0; j < 8; j++) b[j] = Bs[kk][tn + j];
#pragma unroll
            for (int i = 0; i < 8; i++)
#pragma unroll
                for (int j = 0; j < 8; j++) acc[i][j] += a[i] * b[j];
        }
        __syncthreads();
    }
#pragma unroll
    for (int i = 0; i < 8; i++) {
        float* dst = g_y1p + ((size_t)blockIdx.z * N_TOK + m0 + tm + i) * RH + n0 + tn;
#pragma unroll
        for (int j = 0; j < 8; j++) dst[j] = acc[i][j];
    }
}

// ---------------------------------------------------------------------------
// 2) routing: sum partials, +rb1, relu, @rw2+rb2, softmax, top2, scatter
// ---------------------------------------------------------------------------
__global__ void route_kernel(const float* __restrict__ rw2,
                             const float* __restrict__ rb2,
                             const float* __restrict__ rb1) {
    __shared__ float s_w[RH * NE];
    __shared__ float s_b[NE];
    __shared__ float s_b1[RH];
    const int tid = threadIdx.x;
    for (int i = tid; i < RH * NE; i += 256) s_w[i] = rw2[i];
    if (tid < NE) s_b[tid] = rb2[tid];
    if (tid < RH) s_b1[tid] = rb1[tid];
    __syncthreads();

    const int n = blockIdx.x * 256 + tid;

    float acc[NE];
#pragma unroll
    for (int e = 0; e < NE; e++) acc[e] = s_b[e];
    for (int c = 0; c < RH; c++) {
        float vv = 0.0f;
#pragma unroll
        for (int s = 0; s < 8; s++)
            vv += g_y1p[((size_t)s * N_TOK + n) * RH + c];
        float v = fmaxf(vv + s_b1[c], 0.0f);
#pragma unroll
        for (int e = 0; e < NE; e++) acc[e] += v * s_w[c * NE + e];
    }

    float m = acc[0];
#pragma unroll
    for (int e = 1; e < NE; e++) m = fmaxf(m, acc[e]);
    float s = 0.0f, g[NE];
#pragma unroll
    for (int e = 0; e < NE; e++) { g[e] = expf(acc[e] - m); s += g[e]; }
    float inv = 1.0f / s;
#pragma unroll
    for (int e = 0; e < NE; e++) g[e] *= inv;

    int i1 = 0; float g1 = g[0];
#pragma unroll
    for (int e = 1; e < NE; e++) if (g[e] > g1) { g1 = g[e]; i1 = e; }
    int i2 = -1; float g2 = -1.0f;
#pragma unroll
    for (int e = 0; e < NE; e++)
        if (e != i1 && g[e] > g2) { g2 = g[e]; i2 = e; }

    float t  = expf((g2 - g1) * 0.5f);
    float d  = 1.0f / (1.0f + t);
    float w1 = d, w2 = t * d;

    int p1 = atomicAdd(&g_cnt[i1], 1);
    g_ptok[i1 * SEG + p1] = n;
    g_tpos[n * 2] = i1 * SEG + p1; g_tw[n * 2] = w1;
    int p2 = atomicAdd(&g_cnt[i2], 1);
    g_ptok[i2 * SEG + p2] = n;
    g_tpos[n * 2 + 1] = i2 * SEG + p2; g_tw[n * 2 + 1] = w2;
}

// ---------------------------------------------------------------------------
// 3) grouped GEMM1: h = silu(gather(x) @ W1 + b1), split stored.
//    grid (IDIM/128=32, 144), 256 threads, 2 CTAs/SM.
// ---------------------------------------------------------------------------
__global__ void __launch_bounds__(256, 2)
gemm1_k(const float* __restrict__ eb1, const float* __restrict__ sb1) {
    extern __shared__ char smem[];
    const int t = blockIdx.y, n0 = blockIdx.x * 128, tid = threadIdx.x;
    int* s_tok = (int*)(smem + OFF_TOK);

    int e;
    if (t < 128) {
        e = t >> 4;
        int cnt = g_cnt[e];
        int lr0 = (t & 15) * 128;
        if (lr0 >= cnt) return;
        if (tid < 128) {
            int lr = lr0 + tid;
            s_tok[tid] = (lr < cnt) ? g_ptok[e * SEG + lr] : 0;
        }
    } else {
        e = 8;
        if (tid < 128) s_tok[tid] = (t - 128) * 128 + tid;
    }
    __syncthreads();

    const uint32_t smem_base = smem_u32(smem);
    const int tok = s_tok[tid >> 1];
    const char* a_hi = (const char*)g_x_hi + (size_t)tok * CDIM * 2 + (tid & 1) * 32;
    const char* a_lo = (const char*)g_x_lo + (size_t)tok * CDIM * 2 + (tid & 1) * 32;
    const size_t bofs = (((size_t)e * CDIM + (tid >> 3)) * IDIM + n0) * 2 + (tid & 7) * 32;
    const char* b_hi = (const char*)g_w1_hi + bofs;
    const char* b_lo = (const char*)g_w1_lo + bofs;

    GEMM_CORE(CDIM / KC, (size_t)KC * IDIM * 2)

    const float* bias = (e < 8) ? eb1 + (size_t)e * IDIM : sb1;
#pragma unroll
    for (int i = 0; i < 2; i++)
#pragma unroll
        for (int j = 0; j < 8; j++) {
            const int row0 = t * 128 + wm * 32 + i * 16 + (lane >> 2);
            const int col  = n0 + wn * 64 + j * 8 + (lane & 3) * 2;
            float b0 = bias[col], b1 = bias[col + 1];
            float v0 = acc[i][j][0] + b0, v1 = acc[i][j][1] + b1;
            float v2 = acc[i][j][2] + b0, v3 = acc[i][j][3] + b1;
            v0 = v0 / (1.0f + __expf(-v0));
            v1 = v1 / (1.0f + __expf(-v1));
            v2 = v2 / (1.0f + __expf(-v2));
            v3 = v3 / (1.0f + __expf(-v3));
            uint32_t hw, lw;
            size_t idx = ((size_t)row0 * IDIM + col) >> 1;
            SPLIT2(hw, lw, v0, v1);
            g_h_hi[idx] = hw; g_h_lo[idx] = lw;
            size_t idx2 = idx + (size_t)4 * IDIM;   // +8 rows
            SPLIT2(hw, lw, v2, v3);
            g_h_hi[idx2] = hw; g_h_lo[idx2] = lw;
        }
}

// ---------------------------------------------------------------------------
// 4) grouped GEMM2: eo = h @ W2 + b2. grid (CDIM/128=8, 144). K=4096.
// ---------------------------------------------------------------------------
__global__ void __launch_bounds__(256, 2)
gemm2_k(const float* __restrict__ eb2, const float* __restrict__ sb2) {
    extern __shared__ char smem[];
    const int t = blockIdx.y, n0 = blockIdx.x * 128, tid = threadIdx.x;

    int e;
    if (t < 128) {
        e = t >> 4;
        if ((t & 15) * 128 >= g_cnt[e]) return;
    } else {
        e = 8;
    }

    const uint32_t smem_base = smem_u32(smem);
    const int r = t * 128 + (tid >> 1);
    const char* a_hi = (const char*)g_h_hi + (size_t)r * IDIM * 2 + (tid & 1) * 32;
    const char* a_lo = (const char*)g_h_lo + (size_t)r * IDIM * 2 + (tid & 1) * 32;
    const size_t bofs = (((size_t)e * IDIM + (tid >> 3)) * CDIM + n0) * 2 + (tid & 7) * 32;
    const char* b_hi = (const char*)g_w2_hi + bofs;
    const char* b_lo = (const char*)g_w2_lo + bofs;

    GEMM_CORE(IDIM / KC, (size_t)KC * CDIM * 2)

    const float* bias = (e < 8) ? eb2 + (size_t)e * CDIM : sb2;
#pragma unroll
    for (int i = 0; i < 2; i++)
#pragma unroll
        for (int j = 0; j < 8; j++) {
            const int row0 = t * 128 + wm * 32 + i * 16 + (lane >> 2);
            const int col  = n0 + wn * 64 + j * 8 + (lane & 3) * 2;
            float b0 = bias[col], b1 = bias[col + 1];
            float2 lo, hi;
            lo.x = acc[i][j][0] + b0; lo.y = acc[i][j][1] + b1;
            hi.x = acc[i][j][2] + b0; hi.y = acc[i][j][3] + b1;
            *(float2*)(g_eo + (size_t)row0 * CDIM + col) = lo;
            *(float2*)(g_eo + (size_t)(row0 + 8) * CDIM + col) = hi;
        }
}

// ---------------------------------------------------------------------------
// 5) combine: out[n] = eo[shared_n] + w0*eo[pos0] + w1*eo[pos1]
// ---------------------------------------------------------------------------
__global__ void combine_kernel(float* __restrict__ out) {
    int gid = blockIdx.x * 256 + threadIdx.x;
    int n = gid >> 8, c4 = gid & 255;
    const float4* eo = (const float4*)g_eo;
    float4 o = eo[(size_t)(R_EXP + n) * (CDIM / 4) + c4];
    int   p0 = g_tpos[n * 2],     p1 = g_tpos[n * 2 + 1];
    float w0 = g_tw[n * 2],       w1 = g_tw[n * 2 + 1];
    float4 a = eo[(size_t)p0 * (CDIM / 4) + c4];
    float4 b = eo[(size_t)p1 * (CDIM / 4) + c4];
    o.x += w0 * a.x + w1 * b.x;
    o.y += w0 * a.y + w1 * b.y;
    o.z += w0 * a.z + w1 * b.z;
    o.w += w0 * a.w + w1 * b.w;
    ((float4*)out)[gid] = o;
}

// ---------------------------------------------------------------------------
extern "C" void kernel_launch(void* const* d_in, const int* in_sizes, int n_in,
                              void* d_out, int out_size) {
    const float* x   = (const float*)d_in[0];
    const float* rw1 = (const float*)d_in[1];
    const float* rb1 = (const float*)d_in[2];
    const float* rw2 = (const float*)d_in[3];
    const float* rb2 = (const float*)d_in[4];
    const float* ew1 = (const float*)d_in[5];
    const float* eb1 = (const float*)d_in[6];
    const float* ew2 = (const float*)d_in[7];
    const float* eb2 = (const float*)d_in[8];
    const float* sw1 = (const float*)d_in[9];
    const float* sb1 = (const float*)d_in[10];
    const float* sw2 = (const float*)d_in[11];
    const float* sb2 = (const float*)d_in[12];
    float* out = (float*)d_out;

    static bool attr_done = false;
    if (!attr_done) {
        cudaFuncSetAttribute(gemm1_k, cudaFuncAttributeMaxDynamicSharedMemorySize, SMEM_TOTAL);
        cudaFuncSetAttribute(gemm2_k, cudaFuncAttributeMaxDynamicSharedMemorySize, SMEM_TOTAL);
        attr_done = true;
    }

    init_kernel<<<1, 32>>>();
    split_x_k<<<N_TOK * CDIM / 4 / 256, 256>>>(x);
    split_w_k<<<(int)(9 * WPAIRS / 2 / 256), 256>>>(ew1, sw1, 0);
    split_w_k<<<(int)(9 * WPAIRS / 2 / 256), 256>>>(ew2, sw2, 1);
    router_gemm<<<dim3(2, 16, 8), 256>>>(x, rw1);
    route_kernel<<<8, 256>>>(rw2, rb2, rb1);
    gemm1_k<<<dim3(IDIM / 128, MT_TOT), 256, SMEM_TOTAL>>>(eb1, sb1);
    gemm2_k<<<dim3(CDIM / 128, MT_TOT), 256, SMEM_TOTAL>>>(eb2, sb2);
    combine_kernel<<<N_TOK * CDIM / 4 / 256, 256>>>(out);
}